// round 16
// baseline (speedup 1.0000x reference)
#include <cuda_runtime.h>
#include <cuda_bf16.h>
#include <math.h>

// Problem constants
#define HH   1024
#define BB   64
#define SS   512
#define NIN  128
#define NOUT 128

// Fused recurrence config: 128 CTAs = JCH j-chunks x KSP k-splits
#define NCTA 128
#define JCH  4      // j chunks of 256
#define KSP  32     // k splits of 32
#define JW   256    // j per CTA
#define KW   32     // k per CTA
#define RT   512    // threads per CTA (4 warps/SMSP for latency hiding)
#define NMS  (SS + 2)   // 514 macro-steps (layer-1 lags by 2)

typedef unsigned long long u64;

// Scratch (static device memory — no runtime allocation)
__device__ float    g_xp0[(size_t)BB * SS * HH];   // 128 MB: layer-0 input proj
__device__ float    g_h0 [(size_t)BB * SS * HH];   // 128 MB: layer-0 hidden seq
__device__ float    g_h1 [(size_t)BB * SS * HH];   // 128 MB: layer-1 hidden seq
__device__ float    g_p0 [(size_t)KSP * BB * HH];  // 8 MB split-K partials (layer 0)
__device__ float    g_p1 [(size_t)KSP * BB * HH];  // 8 MB split-K partials (layer 1)
__device__ float    g_b1s[HH];                     // bih1 + bhh1
__device__ unsigned g_bar[2 * NMS];                // per-macro-step barrier counters

// ---------------------------------------------------------------------------
// Packed fp32x2 helpers (SASS FFMA2 — only reachable via explicit PTX)
// ---------------------------------------------------------------------------
__device__ __forceinline__ u64 dupf2(float x) {
    u64 r;
    asm("mov.b64 %0, {%1, %1};" : "=l"(r) : "f"(x));
    return r;
}
__device__ __forceinline__ u64 packf2(float lo, float hi) {
    u64 r;
    asm("mov.b64 %0, {%1, %2};" : "=l"(r) : "f"(lo), "f"(hi));
    return r;
}
__device__ __forceinline__ void ffma2(u64& d, u64 a, u64 b) {
    asm("fma.rn.f32x2 %0, %1, %2, %0;" : "+l"(d) : "l"(a), "l"(b));
}
__device__ __forceinline__ u64 addf2(u64 a, u64 b) {
    u64 r;
    asm("add.rn.f32x2 %0, %1, %2;" : "=l"(r) : "l"(a), "l"(b));
    return r;
}

// ---------------------------------------------------------------------------
// Setup: zero barrier counters, precompute b1s = bih1 + bhh1
// ---------------------------------------------------------------------------
__global__ void setup_kernel(const float* __restrict__ bih1,
                             const float* __restrict__ bhh1) {
    int i = blockIdx.x * blockDim.x + threadIdx.x;
    if (i < 2 * NMS) g_bar[i] = 0u;
    if (i < HH) g_b1s[i] = bih1[i] + bhh1[i];
}

// ---------------------------------------------------------------------------
// Grid-wide barrier, single-leader protocol; hot-spin first, then nanosleep
// ---------------------------------------------------------------------------
__device__ __forceinline__ void grid_barrier(int ev) {
    __syncthreads();
    if (threadIdx.x == 0) {
        unsigned* ctr = &g_bar[ev];
        unsigned prev;
        asm volatile("atom.acq_rel.gpu.global.add.u32 %0, [%1], 1;"
                     : "=r"(prev) : "l"(ctr) : "memory");
        if (prev + 1u < (unsigned)NCTA) {
            unsigned v;
            int spins = 0;
            do {
                asm volatile("ld.acquire.gpu.global.u32 %0, [%1];"
                             : "=r"(v) : "l"(ctr) : "memory");
                if (v >= (unsigned)NCTA) break;
                if (++spins > 24) __nanosleep(40);
            } while (true);
        }
    }
    __syncthreads();
}

// ---------------------------------------------------------------------------
// Stage one [64 b x 32 k] slice of a hidden-seq buffer into SMEM, duplicated:
// dst[k*BB + b] = dupf2(seq[b][t][K0+k]).  512 threads: 16B per thread,
// 8 threads = one 128B row segment (coalesced).
// ---------------------------------------------------------------------------
__device__ __forceinline__ void stage_dup(const float* __restrict__ seq, int t,
                                          u64* dst, int row, int sq, int K0) {
    const float4* src = reinterpret_cast<const float4*>(
        seq + ((size_t)row * SS + t) * HH + K0 + sq * 4);
    float4 v = __ldcg(src);
    int k = sq * 4;
    dst[(size_t)(k + 0) * BB + row] = dupf2(v.x);
    dst[(size_t)(k + 1) * BB + row] = dupf2(v.y);
    dst[(size_t)(k + 2) * BB + row] = dupf2(v.z);
    dst[(size_t)(k + 3) * BB + row] = dupf2(v.w);
}

// ---------------------------------------------------------------------------
// One 32-k chunk GEMM: acc[8b][2 j-pairs] += hbuf(dup) x wsX. Pure FFMA2.
// h loads warp-uniform broadcast (4 x LDS.128); w one LDS.128, 16B lane stride.
// ---------------------------------------------------------------------------
__device__ __forceinline__ void gemm_chunk(const float* wsX, const u64* hbuf,
                                           u64 (&acc)[8][2], int b0, int j0) {
#pragma unroll 4
    for (int k = 0; k < KW; ++k) {
        const u64* hrow = hbuf + (size_t)k * BB + b0;   // dup(b0..b0+7)
        ulonglong2 h01 = *reinterpret_cast<const ulonglong2*>(hrow);
        ulonglong2 h23 = *reinterpret_cast<const ulonglong2*>(hrow + 2);
        ulonglong2 h45 = *reinterpret_cast<const ulonglong2*>(hrow + 4);
        ulonglong2 h67 = *reinterpret_cast<const ulonglong2*>(hrow + 6);
        ulonglong2 w  = *reinterpret_cast<const ulonglong2*>(wsX + (size_t)k * JW + j0);
        u64 hd[8] = {h01.x, h01.y, h23.x, h23.y, h45.x, h45.y, h67.x, h67.y};
#pragma unroll
        for (int i = 0; i < 8; ++i) {
            ffma2(acc[i][0], hd[i], w.x);
            ffma2(acc[i][1], hd[i], w.y);
        }
    }
}

// Write split-K partials: part[ks][b][j], one 16B store per b-row
__device__ __forceinline__ void store_partials(float* part, int ks, int b0,
                                               int j0, int J0,
                                               const u64 (&acc)[8][2]) {
    float* pbase = part + (size_t)ks * BB * HH + (size_t)b0 * HH + J0 + j0;
#pragma unroll
    for (int i = 0; i < 8; ++i) {
        ulonglong2 pv;
        pv.x = acc[i][0];
        pv.y = acc[i][1];
        *reinterpret_cast<ulonglong2*>(pbase + (size_t)i * HH) = pv;
    }
}

// ---------------------------------------------------------------------------
// Fused 2-layer pipelined recurrence. Macro-step u (0..513):
//   h0(u)   = tanh(xp0(u)   + h0(u-1) @ Whh0^T)               [u <= 511]
//   h1(u-2) = tanh(b1s + h0(u-2) @ Wih1^T + h1(u-3) @ Whh1^T) [u >= 2]
// CTA (jc, ks): 256-j chunk jc, 32-k segment ks of each GEMM.
// ---------------------------------------------------------------------------
__global__ void __launch_bounds__(RT, 1) fused_rnn_kernel(
        const float* __restrict__ Whh0,
        const float* __restrict__ WihI,
        const float* __restrict__ Whh1) {
    extern __shared__ char smraw[];
    float* ws0 = reinterpret_cast<float*>(smraw);                  // 32 KB
    float* wsI = reinterpret_cast<float*>(smraw + 32768);          // 32 KB
    float* ws1 = reinterpret_cast<float*>(smraw + 65536);          // 32 KB
    u64*   hA0 = reinterpret_cast<u64*>(smraw + 98304);            // 16 KB
    u64*   hA1 = reinterpret_cast<u64*>(smraw + 114688);           // 16 KB
    u64*   hC  = reinterpret_cast<u64*>(smraw + 131072);           // 16 KB

    const int cta = blockIdx.x;
    const int jc  = cta & (JCH - 1);     // 0..3
    const int ks  = cta >> 2;            // 0..31
    const int J0  = jc * JW;
    const int K0  = ks * KW;
    const int tid = threadIdx.x;

    // Load the three weight chunks: W[J0+j][K0+k] -> ws[k][j] (512 threads)
    {
        int j  = tid >> 1;               // 0..255
        int kh = (tid & 1) * 16;         // 0 or 16
        const float4* s0 = reinterpret_cast<const float4*>(Whh0 + (size_t)(J0 + j) * HH + K0 + kh);
        const float4* sI = reinterpret_cast<const float4*>(WihI + (size_t)(J0 + j) * HH + K0 + kh);
        const float4* s1 = reinterpret_cast<const float4*>(Whh1 + (size_t)(J0 + j) * HH + K0 + kh);
#pragma unroll
        for (int q = 0; q < 4; ++q) {
            int k = kh + q * 4;
            float4 v = s0[q];
            ws0[(size_t)(k + 0) * JW + j] = v.x;
            ws0[(size_t)(k + 1) * JW + j] = v.y;
            ws0[(size_t)(k + 2) * JW + j] = v.z;
            ws0[(size_t)(k + 3) * JW + j] = v.w;
            v = sI[q];
            wsI[(size_t)(k + 0) * JW + j] = v.x;
            wsI[(size_t)(k + 1) * JW + j] = v.y;
            wsI[(size_t)(k + 2) * JW + j] = v.z;
            wsI[(size_t)(k + 3) * JW + j] = v.w;
            v = s1[q];
            ws1[(size_t)(k + 0) * JW + j] = v.x;
            ws1[(size_t)(k + 1) * JW + j] = v.y;
            ws1[(size_t)(k + 2) * JW + j] = v.z;
            ws1[(size_t)(k + 3) * JW + j] = v.w;
        }
    }
    __syncthreads();

    // Compute-phase thread tile: 8 batches x 4 j
    const int tx = tid & 63;
    const int ty = tid >> 6;
    const int b0 = ty * 8;
    const int j0 = tx * 4;

    // Reduce slice: 1 element/thread, fully coalesced, j fastest
    const int e0 = cta * 512 + tid;      // 0..65535
    const int rb = e0 >> 10;             // 0..63
    const int rj = e0 & 1023;

    // Staging map: row = batch, sq = 16B strip (8 per row)
    const int srow = tid >> 3;           // 0..63
    const int sq   = tid & 7;            // 0..7

    // Layer-1 bias (constant across steps)
    const float bs = __ldg(g_b1s + rj);

    for (int u = 0; u < NMS; ++u) {
        // Prefetch xp0 for reduce0
        float xv = 0.f;
        if (u <= SS - 1)
            xv = __ldg(g_xp0 + ((size_t)rb * SS + u) * HH + rj);

        // Stage: A = h0(u-1) into ping-pong; C = h1(u-3)
        u64* hAcur = (u & 1) ? hA1 : hA0;
        u64* hAprv = (u & 1) ? hA0 : hA1;   // holds h0(u-2)
        if (u >= 1 && u <= SS) stage_dup(g_h0, u - 1, hAcur, srow, sq, K0);
        if (u >= 3)            stage_dup(g_h1, u - 3, hC,    srow, sq, K0);
        __syncthreads();

        // Partials for layer 0: h0(u-1) @ Whh0 chunk
        if (u >= 1 && u <= SS - 1) {
            u64 acc[8][2];
#pragma unroll
            for (int i = 0; i < 8; ++i) { acc[i][0] = 0ull; acc[i][1] = 0ull; }
            gemm_chunk(ws0, hAcur, acc, b0, j0);
            store_partials(g_p0, ks, b0, j0, J0, acc);
        }

        // Partials for layer 1: h0(u-2) @ Wih1 chunk (+ h1(u-3) @ Whh1 chunk)
        if (u >= 2) {
            u64 acc[8][2];
#pragma unroll
            for (int i = 0; i < 8; ++i) { acc[i][0] = 0ull; acc[i][1] = 0ull; }
            gemm_chunk(wsI, hAprv, acc, b0, j0);
            if (u >= 3) gemm_chunk(ws1, hC, acc, b0, j0);
            store_partials(g_p1, ks, b0, j0, J0, acc);
        }

        grid_barrier(2 * u);   // all partials of macro-step u ready

        // Reduce + tanh (merged loops for both layers in the common case)
        if (u >= 2 && u <= SS - 1) {
            const float* pA = g_p0 + (size_t)rb * HH + rj;
            const float* pB = g_p1 + (size_t)rb * HH + rj;
            float a0 = xv, a1 = 0.f, c0 = bs, c1 = 0.f;
#pragma unroll
            for (int s = 0; s < KSP; s += 2) {
                float x0 = __ldcg(pA + (size_t)s * BB * HH);
                float y0 = __ldcg(pB + (size_t)s * BB * HH);
                float x1 = __ldcg(pA + (size_t)(s + 1) * BB * HH);
                float y1 = __ldcg(pB + (size_t)(s + 1) * BB * HH);
                a0 += x0; c0 += y0; a1 += x1; c1 += y1;
            }
            g_h0[((size_t)rb * SS + u) * HH + rj]       = tanhf(a0 + a1);
            g_h1[((size_t)rb * SS + (u - 2)) * HH + rj] = tanhf(c0 + c1);
        } else {
            if (u <= SS - 1) {
                float a = xv;
                if (u >= 1) {
                    const float* pA = g_p0 + (size_t)rb * HH + rj;
#pragma unroll
                    for (int s = 0; s < KSP; ++s)
                        a += __ldcg(pA + (size_t)s * BB * HH);
                }
                g_h0[((size_t)rb * SS + u) * HH + rj] = tanhf(a);
            }
            if (u >= 2) {
                float c = bs;
                const float* pB = g_p1 + (size_t)rb * HH + rj;
#pragma unroll
                for (int s = 0; s < KSP; ++s)
                    c += __ldcg(pB + (size_t)s * BB * HH);
                g_h1[((size_t)rb * SS + (u - 2)) * HH + rj] = tanhf(c);
            }
        }

        grid_barrier(2 * u + 1);  // outputs of macro-step u fully written
    }
}

// ---------------------------------------------------------------------------
// Tiled fp32 GEMM with bias:  C[M,N] = A[M,K] @ B[N,K]^T + bias1 + bias2
// (phase A only: xp0 = x @ Wih0^T + bih0 + bhh0)
// ---------------------------------------------------------------------------
__global__ void __launch_bounds__(256) gemm_bias_kernel(const float* __restrict__ A,
                                                        const float* __restrict__ Bm,
                                                        const float* __restrict__ bias1,
                                                        const float* __restrict__ bias2,
                                                        float* __restrict__ C,
                                                        int K, int N) {
    constexpr int BM = 128, BN = 128, BK = 16;
    __shared__ float As[BK][BM + 4];
    __shared__ float Bs[BK][BN + 4];

    const int tid   = threadIdx.x;
    const int mBase = blockIdx.y * BM;
    const int nBase = blockIdx.x * BN;
    const int tx = tid & 15;
    const int ty = tid >> 4;
    const int lr = tid >> 2;
    const int lc = (tid & 3) * 4;

    u64 acc[8][4];
#pragma unroll
    for (int i = 0; i < 8; ++i)
#pragma unroll
        for (int p = 0; p < 4; ++p) acc[i][p] = 0ull;

    const int NT = K / BK;
    for (int kt = 0; kt < NT; ++kt) {
#pragma unroll
        for (int h = 0; h < 2; ++h) {
            int r = lr + h * 64;
            float4 va = *reinterpret_cast<const float4*>(
                A + (size_t)(mBase + r) * K + kt * BK + lc);
            As[lc + 0][r] = va.x; As[lc + 1][r] = va.y;
            As[lc + 2][r] = va.z; As[lc + 3][r] = va.w;
            float4 vb = *reinterpret_cast<const float4*>(
                Bm + (size_t)(nBase + r) * K + kt * BK + lc);
            Bs[lc + 0][r] = vb.x; Bs[lc + 1][r] = vb.y;
            Bs[lc + 2][r] = vb.z; Bs[lc + 3][r] = vb.w;
        }
        __syncthreads();

#pragma unroll
        for (int k = 0; k < BK; ++k) {
            float4 a0 = *reinterpret_cast<const float4*>(&As[k][ty * 4]);
            float4 a1 = *reinterpret_cast<const float4*>(&As[k][64 + ty * 4]);
            ulonglong2 bA = *reinterpret_cast<const ulonglong2*>(&Bs[k][tx * 4]);
            ulonglong2 bB = *reinterpret_cast<const ulonglong2*>(&Bs[k][64 + tx * 4]);
            u64 ad[8];
            ad[0] = dupf2(a0.x); ad[1] = dupf2(a0.y);
            ad[2] = dupf2(a0.z); ad[3] = dupf2(a0.w);
            ad[4] = dupf2(a1.x); ad[5] = dupf2(a1.y);
            ad[6] = dupf2(a1.z); ad[7] = dupf2(a1.w);
#pragma unroll
            for (int i = 0; i < 8; ++i) {
                ffma2(acc[i][0], ad[i], bA.x);
                ffma2(acc[i][1], ad[i], bA.y);
                ffma2(acc[i][2], ad[i], bB.x);
                ffma2(acc[i][3], ad[i], bB.y);
            }
        }
        __syncthreads();
    }

    u64 bb[4];
#pragma unroll
    for (int p = 0; p < 4; ++p) {
        int n = nBase + ((p < 2) ? (tx * 4 + p * 2) : (64 + tx * 4 + (p - 2) * 2));
        float v0 = bias1[n];
        float v1 = bias1[n + 1];
        if (bias2) { v0 += bias2[n]; v1 += bias2[n + 1]; }
        bb[p] = packf2(v0, v1);
    }
#pragma unroll
    for (int i = 0; i < 8; ++i) {
        int m = mBase + ((i < 4) ? (ty * 4 + i) : (64 + ty * 4 + (i - 4)));
        ulonglong2 oa, ob;
        oa.x = addf2(acc[i][0], bb[0]); oa.y = addf2(acc[i][1], bb[1]);
        ob.x = addf2(acc[i][2], bb[2]); ob.y = addf2(acc[i][3], bb[3]);
        *reinterpret_cast<ulonglong2*>(C + (size_t)m * N + nBase + tx * 4) = oa;
        *reinterpret_cast<ulonglong2*>(C + (size_t)m * N + nBase + 64 + tx * 4) = ob;
    }
}

// ---------------------------------------------------------------------------
// Final FC: out[b,n] = h1[b, S-1, :] . Wfc[n, :] + bfc[n]
// grid (BB, 4): block handles 32 n for one b; warp-per-row, shfl reduction.
// ---------------------------------------------------------------------------
__global__ void __launch_bounds__(256) fc_kernel(const float* __restrict__ Wfc,
                                                 const float* __restrict__ bfc,
                                                 float* __restrict__ out) {
    __shared__ float hsh[HH];
    const int b = blockIdx.x;
    const float* hrow = g_h1 + ((size_t)b * SS + (SS - 1)) * HH;
    for (int k = threadIdx.x; k < HH; k += 256) hsh[k] = hrow[k];
    __syncthreads();

    const int warp = threadIdx.x >> 5;
    const int lane = threadIdx.x & 31;
    const float4* hv4 = reinterpret_cast<const float4*>(hsh);

    for (int q = 0; q < 4; ++q) {
        int n = blockIdx.y * 32 + q * 8 + warp;
        const float4* w = reinterpret_cast<const float4*>(
            Wfc + (size_t)n * HH) + lane;
        float acc = 0.f;
#pragma unroll
        for (int i = 0; i < 8; ++i) {
            float4 wv = __ldg(w + i * 32);
            float4 hv = hv4[lane + i * 32];
            acc += wv.x * hv.x + wv.y * hv.y + wv.z * hv.z + wv.w * hv.w;
        }
#pragma unroll
        for (int off = 16; off; off >>= 1)
            acc += __shfl_down_sync(0xFFFFFFFFu, acc, off);
        if (lane == 0) out[b * NOUT + n] = acc + bfc[n];
    }
}

// ---------------------------------------------------------------------------
// Entry point
// ---------------------------------------------------------------------------
extern "C" void kernel_launch(void* const* d_in, const int* in_sizes, int n_in,
                              void* d_out, int out_size) {
    const float* x    = (const float*)d_in[0];
    const float* Wih0 = (const float*)d_in[1];
    const float* bih0 = (const float*)d_in[2];
    const float* Whh0 = (const float*)d_in[3];
    const float* bhh0 = (const float*)d_in[4];
    const float* Wih1 = (const float*)d_in[5];
    const float* bih1 = (const float*)d_in[6];
    const float* Whh1 = (const float*)d_in[7];
    const float* bhh1 = (const float*)d_in[8];
    const float* Wfc  = (const float*)d_in[9];
    const float* bfc  = (const float*)d_in[10];
    float* out = (float*)d_out;

    float* xp0 = nullptr;
    cudaGetSymbolAddress((void**)&xp0, g_xp0);

    const int rnn_smem = 147456;  // 3x32KB weights + 3x16KB dup-stage = 144 KB
    cudaFuncSetAttribute(fused_rnn_kernel,
                         cudaFuncAttributeMaxDynamicSharedMemorySize, rnn_smem);

    dim3 gproj(HH / 128, (BB * SS) / 128);  // (8, 256)

    // Phase A: xp0 = x @ Wih0^T + bih0 + bhh0
    gemm_bias_kernel<<<gproj, 256>>>(x, Wih0, bih0, bhh0, xp0, NIN, HH);

    // Setup: barrier counters + layer-1 bias sum
    setup_kernel<<<5, 256>>>(bih1, bhh1);

    // Fused pipelined 2-layer recurrence
    fused_rnn_kernel<<<NCTA, RT, rnn_smem>>>(Whh0, Wih1, Whh1);

    // FC: out = h1[:, S-1, :] @ Wfc^T + bfc
    fc_kernel<<<dim3(BB, 4), 256>>>(Wfc, bfc, out);
}

// round 17
// speedup vs baseline: 1.0819x; 1.0819x over previous
#include <cuda_runtime.h>
#include <cuda_bf16.h>
#include <math.h>

// Problem constants
#define HH   1024
#define BB   64
#define SS   512
#define NIN  128
#define NOUT 128

// Fused recurrence config (R13-measured optimum): 128 CTAs = JCH x KSP
#define NCTA 128
#define JCH  4      // j chunks of 256
#define KSP  32     // k splits of 32
#define JW   256    // j per CTA
#define KW   32     // k per CTA
#define RT   256    // threads per CTA
#define NMS  (SS + 2)   // 514 macro-steps (layer-1 lags by 2)

typedef unsigned long long u64;

// Scratch (static device memory — no runtime allocation)
__device__ float    g_xp0[(size_t)BB * SS * HH];   // 128 MB: layer-0 input proj
__device__ float    g_h0 [(size_t)BB * SS * HH];   // 128 MB: layer-0 hidden seq
__device__ float    g_h1 [(size_t)BB * SS * HH];   // 128 MB: layer-1 hidden seq
__device__ float    g_p0 [(size_t)KSP * BB * HH];  // 8 MB split-K partials (layer 0)
__device__ float    g_p1 [(size_t)KSP * BB * HH];  // 8 MB split-K partials (layer 1)
__device__ float    g_b1s[HH];                     // bih1 + bhh1
__device__ unsigned g_bar[2 * NMS];                // per-macro-step barrier counters

// ---------------------------------------------------------------------------
// Packed fp32x2 helpers (SASS FFMA2 — only reachable via explicit PTX)
// ---------------------------------------------------------------------------
__device__ __forceinline__ u64 dupf2(float x) {
    u64 r;
    asm("mov.b64 %0, {%1, %1};" : "=l"(r) : "f"(x));
    return r;
}
__device__ __forceinline__ u64 packf2(float lo, float hi) {
    u64 r;
    asm("mov.b64 %0, {%1, %2};" : "=l"(r) : "f"(lo), "f"(hi));
    return r;
}
__device__ __forceinline__ void ffma2(u64& d, u64 a, u64 b) {
    asm("fma.rn.f32x2 %0, %1, %2, %0;" : "+l"(d) : "l"(a), "l"(b));
}
__device__ __forceinline__ u64 addf2(u64 a, u64 b) {
    u64 r;
    asm("add.rn.f32x2 %0, %1, %2;" : "=l"(r) : "l"(a), "l"(b));
    return r;
}

// ---------------------------------------------------------------------------
// Setup: zero barrier counters, precompute b1s = bih1 + bhh1
// ---------------------------------------------------------------------------
__global__ void setup_kernel(const float* __restrict__ bih1,
                             const float* __restrict__ bhh1) {
    int i = blockIdx.x * blockDim.x + threadIdx.x;
    if (i < 2 * NMS) g_bar[i] = 0u;
    if (i < HH) g_b1s[i] = bih1[i] + bhh1[i];
}

// ---------------------------------------------------------------------------
// Grid-wide barrier, single-leader protocol; hot-spin first, then nanosleep
// ---------------------------------------------------------------------------
__device__ __forceinline__ void grid_barrier(int ev) {
    __syncthreads();
    if (threadIdx.x == 0) {
        unsigned* ctr = &g_bar[ev];
        unsigned prev;
        asm volatile("atom.acq_rel.gpu.global.add.u32 %0, [%1], 1;"
                     : "=r"(prev) : "l"(ctr) : "memory");
        if (prev + 1u < (unsigned)NCTA) {
            unsigned v;
            int spins = 0;
            do {
                asm volatile("ld.acquire.gpu.global.u32 %0, [%1];"
                             : "=r"(v) : "l"(ctr) : "memory");
                if (v >= (unsigned)NCTA) break;
                if (++spins > 24) __nanosleep(40);
            } while (true);
        }
    }
    __syncthreads();
}

// ---------------------------------------------------------------------------
// Stage one [64 b x 32 k] slice of a hidden-seq buffer into SMEM, duplicated:
// dst[k*BB + b] = dupf2(seq[b][t][K0+k]).  (u64 units: one dup per batch.)
// ---------------------------------------------------------------------------
__device__ __forceinline__ void stage_dup(const float* __restrict__ seq, int t,
                                          u64* dst, int sbb, int sq, int K0) {
    const float4* src = reinterpret_cast<const float4*>(
        seq + ((size_t)sbb * SS + t) * HH + K0 + sq * 8);
    float4 v0 = __ldcg(src);
    float4 v1 = __ldcg(src + 1);
    int k = sq * 8;
    dst[(size_t)(k + 0) * BB + sbb] = dupf2(v0.x);
    dst[(size_t)(k + 1) * BB + sbb] = dupf2(v0.y);
    dst[(size_t)(k + 2) * BB + sbb] = dupf2(v0.z);
    dst[(size_t)(k + 3) * BB + sbb] = dupf2(v0.w);
    dst[(size_t)(k + 4) * BB + sbb] = dupf2(v1.x);
    dst[(size_t)(k + 5) * BB + sbb] = dupf2(v1.y);
    dst[(size_t)(k + 6) * BB + sbb] = dupf2(v1.z);
    dst[(size_t)(k + 7) * BB + sbb] = dupf2(v1.w);
}

// ---------------------------------------------------------------------------
// One 32-k chunk GEMM: acc[8b][4 j-pairs] += hbuf(dup) x wsX. Pure FFMA2.
// h loads are warp-uniform (broadcast); w loads conflict-free 4+4 split.
// ---------------------------------------------------------------------------
__device__ __forceinline__ void gemm_chunk(const float* wsX, const u64* hbuf,
                                           u64 (&acc)[8][4], int b0, int jA, int jB) {
#pragma unroll 4
    for (int k = 0; k < KW; ++k) {
        const u64* hrow = hbuf + (size_t)k * BB + b0;   // dup(b0..b0+7)
        ulonglong2 h01 = *reinterpret_cast<const ulonglong2*>(hrow);
        ulonglong2 h23 = *reinterpret_cast<const ulonglong2*>(hrow + 2);
        ulonglong2 h45 = *reinterpret_cast<const ulonglong2*>(hrow + 4);
        ulonglong2 h67 = *reinterpret_cast<const ulonglong2*>(hrow + 6);
        ulonglong2 wA = *reinterpret_cast<const ulonglong2*>(wsX + (size_t)k * JW + jA);
        ulonglong2 wB = *reinterpret_cast<const ulonglong2*>(wsX + (size_t)k * JW + jB);
        u64 hd[8] = {h01.x, h01.y, h23.x, h23.y, h45.x, h45.y, h67.x, h67.y};
        u64 wv[4] = {wA.x, wA.y, wB.x, wB.y};
#pragma unroll
        for (int i = 0; i < 8; ++i) {
            ffma2(acc[i][0], hd[i], wv[0]);
            ffma2(acc[i][1], hd[i], wv[1]);
            ffma2(acc[i][2], hd[i], wv[2]);
            ffma2(acc[i][3], hd[i], wv[3]);
        }
    }
}

// Write split-K partials: part[ks][b][j], 16B j-pair stores
__device__ __forceinline__ void store_partials(float* part, int ks, int b0,
                                               int jA, int jB, int J0,
                                               const u64 (&acc)[8][4]) {
    float* pbase = part + (size_t)ks * BB * HH + (size_t)b0 * HH + J0;
#pragma unroll
    for (int i = 0; i < 8; ++i) {
        ulonglong2 pa; pa.x = acc[i][0]; pa.y = acc[i][1];
        ulonglong2 pb; pb.x = acc[i][2]; pb.y = acc[i][3];
        *reinterpret_cast<ulonglong2*>(pbase + (size_t)i * HH + jA) = pa;
        *reinterpret_cast<ulonglong2*>(pbase + (size_t)i * HH + jB) = pb;
    }
}

// ---------------------------------------------------------------------------
// Fused 2-layer pipelined recurrence. Macro-step u (0..513):
//   h0(u)   = tanh(xp0(u)   + h0(u-1) @ Whh0^T)               [u <= 511]
//   h1(u-2) = tanh(b1s + h0(u-2) @ Wih1^T + h1(u-3) @ Whh1^T) [u >= 2]
// CTA (jc, ks): 256-j chunk jc, 32-k segment ks of each GEMM.
// ---------------------------------------------------------------------------
__global__ void __launch_bounds__(RT, 1) fused_rnn_kernel(
        const float* __restrict__ Whh0,
        const float* __restrict__ WihI,
        const float* __restrict__ Whh1) {
    extern __shared__ char smraw[];
    float* ws0 = reinterpret_cast<float*>(smraw);                  // 32 KB
    float* wsI = reinterpret_cast<float*>(smraw + 32768);          // 32 KB
    float* ws1 = reinterpret_cast<float*>(smraw + 65536);          // 32 KB
    u64*   hA0 = reinterpret_cast<u64*>(smraw + 98304);            // 16 KB
    u64*   hA1 = reinterpret_cast<u64*>(smraw + 114688);           // 16 KB
    u64*   hC  = reinterpret_cast<u64*>(smraw + 131072);           // 16 KB

    const int cta = blockIdx.x;
    const int jc  = cta & (JCH - 1);     // 0..3
    const int ks  = cta >> 2;            // 0..31
    const int J0  = jc * JW;
    const int K0  = ks * KW;
    const int tid = threadIdx.x;

    // Load the three weight chunks: W[J0+j][K0+k] -> ws[k][j]
    {
        const float4* s0 = reinterpret_cast<const float4*>(Whh0 + (size_t)(J0 + tid) * HH + K0);
        const float4* sI = reinterpret_cast<const float4*>(WihI + (size_t)(J0 + tid) * HH + K0);
        const float4* s1 = reinterpret_cast<const float4*>(Whh1 + (size_t)(J0 + tid) * HH + K0);
#pragma unroll
        for (int q = 0; q < 8; ++q) {
            float4 v = s0[q];
            ws0[(size_t)(q * 4 + 0) * JW + tid] = v.x;
            ws0[(size_t)(q * 4 + 1) * JW + tid] = v.y;
            ws0[(size_t)(q * 4 + 2) * JW + tid] = v.z;
            ws0[(size_t)(q * 4 + 3) * JW + tid] = v.w;
            v = sI[q];
            wsI[(size_t)(q * 4 + 0) * JW + tid] = v.x;
            wsI[(size_t)(q * 4 + 1) * JW + tid] = v.y;
            wsI[(size_t)(q * 4 + 2) * JW + tid] = v.z;
            wsI[(size_t)(q * 4 + 3) * JW + tid] = v.w;
            v = s1[q];
            ws1[(size_t)(q * 4 + 0) * JW + tid] = v.x;
            ws1[(size_t)(q * 4 + 1) * JW + tid] = v.y;
            ws1[(size_t)(q * 4 + 2) * JW + tid] = v.z;
            ws1[(size_t)(q * 4 + 3) * JW + tid] = v.w;
        }
    }
    __syncthreads();

    // Compute-phase thread tile: 8 batches x 8 j (4+4 split)
    const int tx = tid & 31;
    const int ty = tid >> 5;
    const int b0 = ty * 8;
    const int jA = tx * 4;
    const int jB = 128 + tx * 4;

    // Reduce slice: fully coalesced, j fastest over whole [b][j] plane
    const int e0 = cta * 512 + tid * 2;  // 0..65535
    const int rb = e0 >> 10;             // 0..63
    const int rj = e0 & 1023;            // even

    // Staging map
    const int sbb = tid >> 2;            // 0..63 batch row
    const int sq  = tid & 3;             // 0..3 (8-k strips)

    // Layer-1 bias pair (constant across steps)
    const float2 bv = __ldg(reinterpret_cast<const float2*>(g_b1s + rj));

    for (int u = 0; u < NMS; ++u) {
        // Prefetch xp0 pair for reduce0
        float2 xv = make_float2(0.f, 0.f);
        if (u <= SS - 1)
            xv = __ldg(reinterpret_cast<const float2*>(
                g_xp0 + ((size_t)rb * SS + u) * HH + rj));

        // Stage: A = h0(u-1) into ping-pong; C = h1(u-3)
        u64* hAcur = (u & 1) ? hA1 : hA0;
        u64* hAprv = (u & 1) ? hA0 : hA1;   // holds h0(u-2)
        if (u >= 1 && u <= SS) stage_dup(g_h0, u - 1, hAcur, sbb, sq, K0);
        if (u >= 3)            stage_dup(g_h1, u - 3, hC,    sbb, sq, K0);
        __syncthreads();

        // Partials for layer 0: h0(u-1) @ Whh0 chunk
        if (u >= 1 && u <= SS - 1) {
            u64 acc[8][4];
#pragma unroll
            for (int i = 0; i < 8; ++i)
#pragma unroll
                for (int p = 0; p < 4; ++p) acc[i][p] = 0ull;
            gemm_chunk(ws0, hAcur, acc, b0, jA, jB);
            store_partials(g_p0, ks, b0, jA, jB, J0, acc);
        }

        // Partials for layer 1: h0(u-2) @ Wih1 chunk (+ h1(u-3) @ Whh1 chunk)
        if (u >= 2) {
            u64 acc[8][4];
#pragma unroll
            for (int i = 0; i < 8; ++i)
#pragma unroll
                for (int p = 0; p < 4; ++p) acc[i][p] = 0ull;
            gemm_chunk(wsI, hAprv, acc, b0, jA, jB);
            if (u >= 3) gemm_chunk(ws1, hC, acc, b0, jA, jB);
            store_partials(g_p1, ks, b0, jA, jB, J0, acc);
        }

        grid_barrier(2 * u);   // all partials of macro-step u ready

        // Reduce + tanh. Common case (both layers active): merged loops,
        // 4 independent load/accumulate streams for max MLP.
        if (u >= 2 && u <= SS - 1) {
            const float* pA = g_p0 + (size_t)rb * HH + rj;
            const float* pB = g_p1 + (size_t)rb * HH + rj;
            float2 a0 = xv;
            float2 a1 = make_float2(0.f, 0.f);
            float2 c0 = bv;
            float2 c1 = make_float2(0.f, 0.f);
#pragma unroll
            for (int s = 0; s < KSP; s += 2) {
                float2 x0 = __ldcg(reinterpret_cast<const float2*>(pA + (size_t)s * BB * HH));
                float2 y0 = __ldcg(reinterpret_cast<const float2*>(pB + (size_t)s * BB * HH));
                float2 x1 = __ldcg(reinterpret_cast<const float2*>(pA + (size_t)(s + 1) * BB * HH));
                float2 y1 = __ldcg(reinterpret_cast<const float2*>(pB + (size_t)(s + 1) * BB * HH));
                a0.x += x0.x; a0.y += x0.y;
                c0.x += y0.x; c0.y += y0.y;
                a1.x += x1.x; a1.y += x1.y;
                c1.x += y1.x; c1.y += y1.y;
            }
            float2 hv0, hv1;
            hv0.x = tanhf(a0.x + a1.x);
            hv0.y = tanhf(a0.y + a1.y);
            hv1.x = tanhf(c0.x + c1.x);
            hv1.y = tanhf(c0.y + c1.y);
            *reinterpret_cast<float2*>(g_h0 + ((size_t)rb * SS + u) * HH + rj) = hv0;
            *reinterpret_cast<float2*>(g_h1 + ((size_t)rb * SS + (u - 2)) * HH + rj) = hv1;
        } else {
            if (u <= SS - 1) {
                float v0 = xv.x, v1 = xv.y;
                if (u >= 1) {
                    const float* pA = g_p0 + (size_t)rb * HH + rj;
#pragma unroll
                    for (int s = 0; s < KSP; ++s) {
                        float2 p = __ldcg(reinterpret_cast<const float2*>(
                            pA + (size_t)s * BB * HH));
                        v0 += p.x;
                        v1 += p.y;
                    }
                }
                float2 hv;
                hv.x = tanhf(v0);
                hv.y = tanhf(v1);
                *reinterpret_cast<float2*>(g_h0 + ((size_t)rb * SS + u) * HH + rj) = hv;
            }
            if (u >= 2) {
                float v0 = bv.x, v1 = bv.y;
                const float* pB = g_p1 + (size_t)rb * HH + rj;
#pragma unroll
                for (int s = 0; s < KSP; ++s) {
                    float2 p = __ldcg(reinterpret_cast<const float2*>(
                        pB + (size_t)s * BB * HH));
                    v0 += p.x;
                    v1 += p.y;
                }
                float2 hv;
                hv.x = tanhf(v0);
                hv.y = tanhf(v1);
                *reinterpret_cast<float2*>(g_h1 + ((size_t)rb * SS + (u - 2)) * HH + rj) = hv;
            }
        }

        grid_barrier(2 * u + 1);  // outputs of macro-step u fully written
    }
}

// ---------------------------------------------------------------------------
// Tiled fp32 GEMM with bias:  C[M,N] = A[M,K] @ B[N,K]^T + bias1 + bias2
// (phase A only: xp0 = x @ Wih0^T + bih0 + bhh0)
// ---------------------------------------------------------------------------
__global__ void __launch_bounds__(256) gemm_bias_kernel(const float* __restrict__ A,
                                                        const float* __restrict__ Bm,
                                                        const float* __restrict__ bias1,
                                                        const float* __restrict__ bias2,
                                                        float* __restrict__ C,
                                                        int K, int N) {
    constexpr int BM = 128, BN = 128, BK = 16;
    __shared__ float As[BK][BM + 4];
    __shared__ float Bs[BK][BN + 4];

    const int tid   = threadIdx.x;
    const int mBase = blockIdx.y * BM;
    const int nBase = blockIdx.x * BN;
    const int tx = tid & 15;
    const int ty = tid >> 4;
    const int lr = tid >> 2;
    const int lc = (tid & 3) * 4;

    u64 acc[8][4];
#pragma unroll
    for (int i = 0; i < 8; ++i)
#pragma unroll
        for (int p = 0; p < 4; ++p) acc[i][p] = 0ull;

    const int NT = K / BK;
    for (int kt = 0; kt < NT; ++kt) {
#pragma unroll
        for (int h = 0; h < 2; ++h) {
            int r = lr + h * 64;
            float4 va = *reinterpret_cast<const float4*>(
                A + (size_t)(mBase + r) * K + kt * BK + lc);
            As[lc + 0][r] = va.x; As[lc + 1][r] = va.y;
            As[lc + 2][r] = va.z; As[lc + 3][r] = va.w;
            float4 vb = *reinterpret_cast<const float4*>(
                Bm + (size_t)(nBase + r) * K + kt * BK + lc);
            Bs[lc + 0][r] = vb.x; Bs[lc + 1][r] = vb.y;
            Bs[lc + 2][r] = vb.z; Bs[lc + 3][r] = vb.w;
        }
        __syncthreads();

#pragma unroll
        for (int k = 0; k < BK; ++k) {
            float4 a0 = *reinterpret_cast<const float4*>(&As[k][ty * 4]);
            float4 a1 = *reinterpret_cast<const float4*>(&As[k][64 + ty * 4]);
            ulonglong2 bA = *reinterpret_cast<const ulonglong2*>(&Bs[k][tx * 4]);
            ulonglong2 bB = *reinterpret_cast<const ulonglong2*>(&Bs[k][64 + tx * 4]);
            u64 ad[8];
            ad[0] = dupf2(a0.x); ad[1] = dupf2(a0.y);
            ad[2] = dupf2(a0.z); ad[3] = dupf2(a0.w);
            ad[4] = dupf2(a1.x); ad[5] = dupf2(a1.y);
            ad[6] = dupf2(a1.z); ad[7] = dupf2(a1.w);
#pragma unroll
            for (int i = 0; i < 8; ++i) {
                ffma2(acc[i][0], ad[i], bA.x);
                ffma2(acc[i][1], ad[i], bA.y);
                ffma2(acc[i][2], ad[i], bB.x);
                ffma2(acc[i][3], ad[i], bB.y);
            }
        }
        __syncthreads();
    }

    u64 bb[4];
#pragma unroll
    for (int p = 0; p < 4; ++p) {
        int n = nBase + ((p < 2) ? (tx * 4 + p * 2) : (64 + tx * 4 + (p - 2) * 2));
        float v0 = bias1[n];
        float v1 = bias1[n + 1];
        if (bias2) { v0 += bias2[n]; v1 += bias2[n + 1]; }
        bb[p] = packf2(v0, v1);
    }
#pragma unroll
    for (int i = 0; i < 8; ++i) {
        int m = mBase + ((i < 4) ? (ty * 4 + i) : (64 + ty * 4 + (i - 4)));
        ulonglong2 oa, ob;
        oa.x = addf2(acc[i][0], bb[0]); oa.y = addf2(acc[i][1], bb[1]);
        ob.x = addf2(acc[i][2], bb[2]); ob.y = addf2(acc[i][3], bb[3]);
        *reinterpret_cast<ulonglong2*>(C + (size_t)m * N + nBase + tx * 4) = oa;
        *reinterpret_cast<ulonglong2*>(C + (size_t)m * N + nBase + 64 + tx * 4) = ob;
    }
}

// ---------------------------------------------------------------------------
// Final FC: out[b,n] = h1[b, S-1, :] . Wfc[n, :] + bfc[n]
// grid (BB, 4): block handles 32 n for one b; warp-per-row, shfl reduction.
// ---------------------------------------------------------------------------
__global__ void __launch_bounds__(256) fc_kernel(const float* __restrict__ Wfc,
                                                 const float* __restrict__ bfc,
                                                 float* __restrict__ out) {
    __shared__ float hsh[HH];
    const int b = blockIdx.x;
    const float* hrow = g_h1 + ((size_t)b * SS + (SS - 1)) * HH;
    for (int k = threadIdx.x; k < HH; k += 256) hsh[k] = hrow[k];
    __syncthreads();

    const int warp = threadIdx.x >> 5;
    const int lane = threadIdx.x & 31;
    const float4* hv4 = reinterpret_cast<const float4*>(hsh);

    for (int q = 0; q < 4; ++q) {
        int n = blockIdx.y * 32 + q * 8 + warp;
        const float4* w = reinterpret_cast<const float4*>(
            Wfc + (size_t)n * HH) + lane;
        float acc = 0.f;
#pragma unroll
        for (int i = 0; i < 8; ++i) {
            float4 wv = __ldg(w + i * 32);
            float4 hv = hv4[lane + i * 32];
            acc += wv.x * hv.x + wv.y * hv.y + wv.z * hv.z + wv.w * hv.w;
        }
#pragma unroll
        for (int off = 16; off; off >>= 1)
            acc += __shfl_down_sync(0xFFFFFFFFu, acc, off);
        if (lane == 0) out[b * NOUT + n] = acc + bfc[n];
    }
}

// ---------------------------------------------------------------------------
// Entry point
// ---------------------------------------------------------------------------
extern "C" void kernel_launch(void* const* d_in, const int* in_sizes, int n_in,
                              void* d_out, int out_size) {
    const float* x    = (const float*)d_in[0];
    const float* Wih0 = (const float*)d_in[1];
    const float* bih0 = (const float*)d_in[2];
    const float* Whh0 = (const float*)d_in[3];
    const float* bhh0 = (const float*)d_in[4];
    const float* Wih1 = (const float*)d_in[5];
    const float* bih1 = (const float*)d_in[6];
    const float* Whh1 = (const float*)d_in[7];
    const float* bhh1 = (const float*)d_in[8];
    const float* Wfc  = (const float*)d_in[9];
    const float* bfc  = (const float*)d_in[10];
    float* out = (float*)d_out;

    float* xp0 = nullptr;
    cudaGetSymbolAddress((void**)&xp0, g_xp0);

    const int rnn_smem = 147456;  // 3x32KB weights + 3x16KB dup-stage = 144 KB
    cudaFuncSetAttribute(fused_rnn_kernel,
                         cudaFuncAttributeMaxDynamicSharedMemorySize, rnn_smem);

    dim3 gproj(HH / 128, (BB * SS) / 128);  // (8, 256)

    // Phase A: xp0 = x @ Wih0^T + bih0 + bhh0
    gemm_bias_kernel<<<gproj, 256>>>(x, Wih0, bih0, bhh0, xp0, NIN, HH);

    // Setup: barrier counters + layer-1 bias sum
    setup_kernel<<<5, 256>>>(bih1, bhh1);

    // Fused pipelined 2-layer recurrence
    fused_rnn_kernel<<<NCTA, RT, rnn_smem>>>(Whh0, Wih1, Whh1);

    // FC: out = h1[:, S-1, :] @ Wfc^T + bfc
    fc_kernel<<<dim3(BB, 4), 256>>>(Wfc, bfc, out);
}